// round 12
// baseline (speedup 1.0000x reference)
#include <cuda_runtime.h>
#include <cuda_bf16.h>
#include <cstdint>

#define BB 8
#define NTOK 12560
#define HW 12544
#define CDIM 256
#define NADD 16
#define NHEAD 8
#define HD 32
#define GW 112
#define TWIN 49
#define SCALE 0.17677669529663687f

// ---------------- scratch (device globals; no allocations allowed) ----------
__device__ float g_qkv1[(size_t)BB * NTOK * 768];
__device__ float g_qkv2[(size_t)BB * HW * 768];
__device__ float g_part[1024 * 16 * 34];
__device__ float g_oadd[BB * NADD * CDIM];
// bf16 split operands
__device__ __nv_bfloat16 g_Ah[(size_t)100480 * 256];
__device__ __nv_bfloat16 g_Al[(size_t)100480 * 256];
__device__ __nv_bfloat16 g_Bh[(size_t)100352 * 256];
__device__ __nv_bfloat16 g_Bl[(size_t)100352 * 256];
__device__ __nv_bfloat16 g_Wqh[768 * 256], g_Wql[768 * 256];
__device__ __nv_bfloat16 g_Wph[256 * 256], g_Wpl[256 * 256];

__constant__ float c_rope_inv[8] = {
    1.0f, 0.5623413251903491f, 0.31622776601683794f, 0.17782794100389228f,
    0.1f, 0.05623413251903491f, 0.031622776601683794f, 0.017782794100389227f};

// ================= fp32 -> (bf16 hi, bf16 lo) split =========================
__device__ __forceinline__ void cvt2(float v, __nv_bfloat16& h, __nv_bfloat16& l) {
    h = __float2bfloat16_rn(v);
    l = __float2bfloat16_rn(v - __bfloat162float(h));
}
__global__ void conv_pair_k(const float* __restrict__ src,
                            __nv_bfloat16* __restrict__ dh,
                            __nv_bfloat16* __restrict__ dl,
                            int n4)
{
    const int i = blockIdx.x * 256 + threadIdx.x;
    if (i >= n4) return;
    const int e0 = i * 4;
    const float4 v = *(const float4*)(src + e0);
    __nv_bfloat16 h0, l0, h1, l1, h2, l2, h3, l3;
    cvt2(v.x, h0, l0); cvt2(v.y, h1, l1); cvt2(v.z, h2, l2); cvt2(v.w, h3, l3);
    __nv_bfloat162* ph = (__nv_bfloat162*)(dh + e0);
    __nv_bfloat162* pl = (__nv_bfloat162*)(dl + e0);
    ph[0] = __halves2bfloat162(h0, h1); ph[1] = __halves2bfloat162(h2, h3);
    pl[0] = __halves2bfloat162(l0, l1); pl[1] = __halves2bfloat162(l2, l3);
}

// ================= shared PTX helpers ========================================
#define CP16(saddr, gptr) \
    asm volatile("cp.async.ca.shared.global [%0], [%1], 16;" :: "r"(saddr), "l"(gptr))
#define CP_COMMIT() asm volatile("cp.async.commit_group;")
#define CP_WAIT1()  asm volatile("cp.async.wait_group 1;")
#define CP_WAIT0()  asm volatile("cp.async.wait_group 0;")

#define LDMX4(r0_, r1_, r2_, r3_, addr_) \
    asm volatile("ldmatrix.sync.aligned.m8n8.x4.shared.b16 {%0,%1,%2,%3}, [%4];" \
        : "=r"(r0_), "=r"(r1_), "=r"(r2_), "=r"(r3_) : "r"(addr_))

#define MMA16816(c_, a_, b0_, b1_) \
    asm volatile("mma.sync.aligned.m16n8k16.row.col.f32.bf16.bf16.f32 " \
        "{%0,%1,%2,%3}, {%4,%5,%6,%7}, {%8,%9}, {%0,%1,%2,%3};" \
        : "+f"((c_)[0]), "+f"((c_)[1]), "+f"((c_)[2]), "+f"((c_)[3]) \
        : "r"((a_)[0]), "r"((a_)[1]), "r"((a_)[2]), "r"((a_)[3]), \
          "r"(b0_), "r"(b1_))

__device__ __forceinline__ uint32_t smem_u32(const void* p) {
    uint32_t a;
    asm("{ .reg .u64 t; cvta.to.shared.u64 t, %1; cvt.u32.u64 %0, t; }" : "=r"(a) : "l"(p));
    return a;
}

// ================= mma.sync bf16x3 GEMM =====================================
#define MATB 10240
#define BUFB (4 * MATB)
#define GSM_TOT (1024 + 2 * BUFB)

__global__ void __launch_bounds__(256, 2) tgemm_k(
    const __nv_bfloat16* __restrict__ Ah, const __nv_bfloat16* __restrict__ Al,
    const __nv_bfloat16* __restrict__ Wh, const __nv_bfloat16* __restrict__ Wl,
    const float* __restrict__ bias, float* __restrict__ Out,
    __nv_bfloat16* __restrict__ oah, __nv_bfloat16* __restrict__ oal,
    int nout, int out_mode)
{
    extern __shared__ char smem[];
    float* sbias = (float*)smem;
    const int tid = threadIdx.x;
    const int lane = tid & 31, wid = tid >> 5;
    const int wm = wid & 3, wn = wid >> 2;
    const int c0 = blockIdx.x * 128, r0 = blockIdx.y * 128;

    if (tid < 128) sbias[tid] = bias[c0 + tid];

    const uint32_t sbase = smem_u32(smem) + 1024;
    const int ldrow = tid >> 2;
    const int ldseg = tid & 3;

    auto load_chunk = [&](int ck, int buf) {
        const uint32_t b = sbase + buf * BUFB;
        const int koff = ck * 32 + ldseg * 8;
#pragma unroll
        for (int i = 0; i < 2; i++) {
            const int row = ldrow + i * 64;
            const uint32_t so = row * 80 + ldseg * 16;
            const size_t ga = (size_t)(r0 + row) * 256 + koff;
            const size_t gw = (size_t)(c0 + row) * 256 + koff;
            CP16(b + 0 * MATB + so, Ah + ga);
            CP16(b + 1 * MATB + so, Al + ga);
            CP16(b + 2 * MATB + so, Wh + gw);
            CP16(b + 3 * MATB + so, Wl + gw);
        }
        CP_COMMIT();
    };

    float acc[2][8][4];
#pragma unroll
    for (int i = 0; i < 2; i++)
#pragma unroll
        for (int j = 0; j < 8; j++)
#pragma unroll
            for (int k = 0; k < 4; k++) acc[i][j][k] = 0.f;

    load_chunk(0, 0);

    for (int ck = 0; ck < 8; ck++) {
        if (ck < 7) load_chunk(ck + 1, (ck + 1) & 1);
        if (ck < 7) { CP_WAIT1(); } else { CP_WAIT0(); }
        __syncthreads();

        const uint32_t b = sbase + (ck & 1) * BUFB;
        const int arow = wm * 32 + (lane & 15);
        const int acol8 = (lane >> 4) * 8;
        const int nrow = wn * 64 + ((lane >> 4) << 3) + (lane & 7);
        const int kcol8 = ((lane >> 3) & 1) * 8;

#pragma unroll
        for (int ks = 0; ks < 2; ks++) {
            const int kc = ks * 16;
            uint32_t ah[2][4], al[2][4];
#pragma unroll
            for (int mf = 0; mf < 2; mf++) {
                const uint32_t aaddr = b + (uint32_t)(arow + mf * 16) * 80 + (uint32_t)(kc + acol8) * 2;
                LDMX4(ah[mf][0], ah[mf][1], ah[mf][2], ah[mf][3], aaddr);
                LDMX4(al[mf][0], al[mf][1], al[mf][2], al[mf][3], aaddr + MATB);
            }
#pragma unroll
            for (int nf2 = 0; nf2 < 4; nf2++) {
                const uint32_t waddr = b + 2 * MATB
                    + (uint32_t)(nrow + nf2 * 16) * 80 + (uint32_t)(kc + kcol8) * 2;
                uint32_t wh[4], wl[4];
                LDMX4(wh[0], wh[1], wh[2], wh[3], waddr);
                LDMX4(wl[0], wl[1], wl[2], wl[3], waddr + MATB);
#pragma unroll
                for (int mf = 0; mf < 2; mf++) {
                    MMA16816(acc[mf][nf2 * 2],     ah[mf], wh[0], wh[1]);
                    MMA16816(acc[mf][nf2 * 2 + 1], ah[mf], wh[2], wh[3]);
                    MMA16816(acc[mf][nf2 * 2],     ah[mf], wl[0], wl[1]);
                    MMA16816(acc[mf][nf2 * 2 + 1], ah[mf], wl[2], wl[3]);
                    MMA16816(acc[mf][nf2 * 2],     al[mf], wh[0], wh[1]);
                    MMA16816(acc[mf][nf2 * 2 + 1], al[mf], wh[2], wh[3]);
                }
            }
        }
        __syncthreads();
    }

    // ---- epilogue ----
#pragma unroll
    for (int mf = 0; mf < 2; mf++) {
        const int rA = r0 + wm * 32 + mf * 16 + (lane >> 2);
#pragma unroll
        for (int nf = 0; nf < 8; nf++) {
            const int cb = wn * 64 + nf * 8 + (lane & 3) * 2;
            const float bv0 = sbias[cb], bv1 = sbias[cb + 1];
#pragma unroll
            for (int hh = 0; hh < 2; hh++) {
                const int r = rA + hh * 8;
                size_t ob;
                if (out_mode == 0) ob = (size_t)r * nout + c0 + cb;
                else               ob = ((size_t)r + (size_t)(r / HW) * NADD) * 256 + c0 + cb;
                const float v0 = acc[mf][nf][hh * 2]     + bv0;
                const float v1 = acc[mf][nf][hh * 2 + 1] + bv1;
                if (out_mode == 2) {
                    float2 o = *(float2*)(Out + ob);
                    o.x += 0.5f * v0; o.y += 0.5f * v1;
                    *(float2*)(Out + ob) = o;
                } else {
                    *(float2*)(Out + ob) = make_float2(v0, v1);
                    if (out_mode == 1) {
                        __nv_bfloat16 h0, l0, h1, l1;
                        cvt2(v0, h0, l0); cvt2(v1, h1, l1);
                        const size_t db = (size_t)r * 256 + c0 + cb;
                        *(__nv_bfloat162*)(oah + db) = __halves2bfloat162(h0, h1);
                        *(__nv_bfloat162*)(oal + db) = __halves2bfloat162(l0, l1);
                    }
                }
            }
        }
    }
}

// ---------------- windowed attention via mma.sync (bf16x3) ------------------
// Block = (window, head), 128 threads / 4 warps (warp = m-tile of 16 rows).
// smem layout (dynamic, 46080 B):
//   [0, 16384):      qs[49][36], ks[49][36] fp32   -> reused as S[64][64] fp32
//   [16384, 25600):  VTh[32][72], VTl[32][72] bf16 (V transposed, pads zeroed)
//   [25600, 46080):  QBh/QBl/KBh/KBl [64][40] bf16 -> reused as PBh/PBl [64][72]
#define WA_SMEM 46080
__global__ void __launch_bounds__(128) winattn_k(const int* __restrict__ pos2d)
{
    extern __shared__ char wsm[];
    float* qs = (float*)wsm;                          // [49][36]
    float* ks = qs + 49 * 36;
    float* S  = (float*)wsm;                          // [64][64] (reuse)
    __nv_bfloat16* VTh = (__nv_bfloat16*)(wsm + 16384);
    __nv_bfloat16* VTl = (__nv_bfloat16*)(wsm + 20992);
    __nv_bfloat16* QBh = (__nv_bfloat16*)(wsm + 25600);
    __nv_bfloat16* QBl = (__nv_bfloat16*)(wsm + 30720);
    __nv_bfloat16* KBh = (__nv_bfloat16*)(wsm + 35840);
    __nv_bfloat16* KBl = (__nv_bfloat16*)(wsm + 40960);
    __nv_bfloat16* PBh = (__nv_bfloat16*)(wsm + 25600);  // reuse
    __nv_bfloat16* PBl = (__nv_bfloat16*)(wsm + 34816);

    const uint32_t sb   = smem_u32(wsm);
    const uint32_t uVTh = sb + 16384, uVTl = sb + 20992;
    const uint32_t uQBh = sb + 25600, uQBl = sb + 30720;
    const uint32_t uKBh = sb + 35840, uKBl = sb + 40960;
    const uint32_t uPBh = sb + 25600, uPBl = sb + 34816;

    const int h = blockIdx.x & 7;
    const int wid = blockIdx.x >> 3;
    const int b = wid >> 8;
    const int w = wid & 255;
    const int wh = w >> 4, ww = w & 15;
    const int tid = threadIdx.x, lane = tid & 31, wrp = tid >> 5;

    // ---- P0: zero VT region; load q,k fp32 ----
    {
        uint4 z = make_uint4(0, 0, 0, 0);
        uint4* vz = (uint4*)(wsm + 16384);
        for (int i = tid; i < 576; i += 128) vz[i] = z;
    }
    for (int e = tid; e < TWIN * 16; e += 128) {
        const int t = e >> 4, seg = e & 15;
        const int mat = seg >> 3, d4 = seg & 7;
        const int n = (wh * 7 + t / 7) * GW + ww * 7 + (t % 7);
        const float4 v = *(const float4*)(g_qkv1 + ((size_t)b * NTOK + n) * 768
                                          + h * 32 + mat * 256 + d4 * 4);
        float* dst = mat ? ks : qs;
        *(float4*)&dst[t * 36 + d4 * 4] = v;
    }
    __syncthreads();

    // ---- P1: rope q,k (in fp32 smem) + load/convert V transposed ----
    for (int e = tid; e < TWIN * 16; e += 128) {
        const int t = e >> 4, pi = e & 15;
        const int hh = pi >> 3, i = pi & 7;
        const int n = (wh * 7 + t / 7) * GW + ww * 7 + (t % 7);
        const int pos = pos2d[((size_t)b * NTOK + n) * 2 + hh];
        float sn, cs;
        sincosf((float)pos * c_rope_inv[i], &sn, &cs);
        const int base = t * 36 + hh * 16 + i;
        const float q0 = qs[base], q1 = qs[base + 8];
        qs[base] = q0 * cs - q1 * sn; qs[base + 8] = q1 * cs + q0 * sn;
        const float k0 = ks[base], k1 = ks[base + 8];
        ks[base] = k0 * cs - k1 * sn; ks[base + 8] = k1 * cs + k0 * sn;
    }
    for (int e = tid; e < TWIN * 32; e += 128) {
        const int j = e >> 5, d = e & 31;
        const int n = (wh * 7 + j / 7) * GW + ww * 7 + (j % 7);
        const float v = g_qkv1[((size_t)b * NTOK + n) * 768 + 512 + h * 32 + d];
        __nv_bfloat16 hv, lv; cvt2(v, hv, lv);
        VTh[d * 72 + j] = hv; VTl[d * 72 + j] = lv;
    }
    __syncthreads();

    // ---- P2: convert rope'd q,k -> bf16 hi/lo tiles (zero-pad rows >= 49) ----
    for (int e = tid; e < 2048; e += 128) {
        const int row = e >> 5, d = e & 31;
        float qv = 0.f, kv = 0.f;
        if (row < TWIN) { qv = qs[row * 36 + d]; kv = ks[row * 36 + d]; }
        __nv_bfloat16 hq, lq, hk, lk;
        cvt2(qv, hq, lq); cvt2(kv, hk, lk);
        QBh[row * 40 + d] = hq; QBl[row * 40 + d] = lq;
        KBh[row * 40 + d] = hk; KBl[row * 40 + d] = lk;
    }
    __syncthreads();

    // ---- P3: S = Q K^T (bf16x3), warp = 16-row m-tile ----
    {
        const int arow = wrp * 16 + (lane & 15);
        const int acol8 = (lane >> 4) * 8;
        const int brow = ((lane >> 4) << 3) + (lane & 7);
        const int kcol8 = ((lane >> 3) & 1) * 8;
        float acc[8][4];
#pragma unroll
        for (int i = 0; i < 8; i++)
#pragma unroll
            for (int k = 0; k < 4; k++) acc[i][k] = 0.f;
#pragma unroll
        for (int kh = 0; kh < 2; kh++) {
            const int kc = kh * 16;
            uint32_t ah[4], al4[4];
            const uint32_t aoff = (uint32_t)arow * 80 + (uint32_t)(kc + acol8) * 2;
            LDMX4(ah[0], ah[1], ah[2], ah[3], uQBh + aoff);
            LDMX4(al4[0], al4[1], al4[2], al4[3], uQBl + aoff);
#pragma unroll
            for (int np = 0; np < 4; np++) {
                const uint32_t boff = (uint32_t)(np * 16 + brow) * 80 + (uint32_t)(kc + kcol8) * 2;
                uint32_t bh[4], bl[4];
                LDMX4(bh[0], bh[1], bh[2], bh[3], uKBh + boff);
                LDMX4(bl[0], bl[1], bl[2], bl[3], uKBl + boff);
                MMA16816(acc[np * 2],     ah,  bh[0], bh[1]);
                MMA16816(acc[np * 2 + 1], ah,  bh[2], bh[3]);
                MMA16816(acc[np * 2],     ah,  bl[0], bl[1]);
                MMA16816(acc[np * 2 + 1], ah,  bl[2], bl[3]);
                MMA16816(acc[np * 2],     al4, bh[0], bh[1]);
                MMA16816(acc[np * 2 + 1], al4, bh[2], bh[3]);
            }
        }
        const int r0 = wrp * 16 + (lane >> 2);
        const int cbase = (lane & 3) * 2;
#pragma unroll
        for (int nt = 0; nt < 8; nt++) {
            const int col = nt * 8 + cbase;
            S[r0 * 64 + col]       = acc[nt][0] * SCALE;
            S[r0 * 64 + col + 1]   = acc[nt][1] * SCALE;
            S[(r0 + 8) * 64 + col]     = acc[nt][2] * SCALE;
            S[(r0 + 8) * 64 + col + 1] = acc[nt][3] * SCALE;
        }
    }
    __syncthreads();

    // ---- P4: softmax rows (warp per row) ----
#pragma unroll
    for (int rr = 0; rr < 13; rr++) {
        const int row = wrp + rr * 4;
        if (row < TWIN) {
            const float v0 = S[row * 64 + lane];
            const float v1 = (lane + 32 < TWIN) ? S[row * 64 + lane + 32] : -1e30f;
            float m = fmaxf(v0, v1);
#pragma unroll
            for (int o = 16; o > 0; o >>= 1) m = fmaxf(m, __shfl_xor_sync(~0u, m, o));
            const float e0 = __expf(v0 - m);
            const float e1 = (lane + 32 < TWIN) ? __expf(v1 - m) : 0.f;
            float s = e0 + e1;
#pragma unroll
            for (int o = 16; o > 0; o >>= 1) s += __shfl_xor_sync(~0u, s, o);
            const float inv = 1.f / s;
            S[row * 64 + lane] = e0 * inv;
            if (lane + 32 < TWIN) S[row * 64 + lane + 32] = e1 * inv;
        }
    }
    __syncthreads();

    // ---- P5: P -> bf16 hi/lo [64][72], pads exactly zero ----
    for (int e = tid; e < 4096; e += 128) {
        const int row = e >> 6, col = e & 63;
        const float v = (row < TWIN && col < TWIN) ? S[row * 64 + col] : 0.f;
        __nv_bfloat16 hp, lp; cvt2(v, hp, lp);
        PBh[row * 72 + col] = hp; PBl[row * 72 + col] = lp;
    }
    __syncthreads();

    // ---- P6: O = P V (bf16x3) + epilogue ----
    {
        const int arow = wrp * 16 + (lane & 15);
        const int acol8 = (lane >> 4) * 8;
        const int brow = ((lane >> 4) << 3) + (lane & 7);
        const int kcol8 = ((lane >> 3) & 1) * 8;
        float oacc[4][4];
#pragma unroll
        for (int i = 0; i < 4; i++)
#pragma unroll
            for (int k = 0; k < 4; k++) oacc[i][k] = 0.f;
#pragma unroll
        for (int ks4 = 0; ks4 < 4; ks4++) {
            const int kc = ks4 * 16;
            uint32_t ph[4], pl[4];
            const uint32_t aoff = (uint32_t)arow * 144 + (uint32_t)(kc + acol8) * 2;
            LDMX4(ph[0], ph[1], ph[2], ph[3], uPBh + aoff);
            LDMX4(pl[0], pl[1], pl[2], pl[3], uPBl + aoff);
#pragma unroll
            for (int np = 0; np < 2; np++) {
                const uint32_t boff = (uint32_t)(np * 16 + brow) * 144 + (uint32_t)(kc + kcol8) * 2;
                uint32_t vh[4], vl[4];
                LDMX4(vh[0], vh[1], vh[2], vh[3], uVTh + boff);
                LDMX4(vl[0], vl[1], vl[2], vl[3], uVTl + boff);
                MMA16816(oacc[np * 2],     ph, vh[0], vh[1]);
                MMA16816(oacc[np * 2 + 1], ph, vh[2], vh[3]);
                MMA16816(oacc[np * 2],     ph, vl[0], vl[1]);
                MMA16816(oacc[np * 2 + 1], ph, vl[2], vl[3]);
                MMA16816(oacc[np * 2],     pl, vh[0], vh[1]);
                MMA16816(oacc[np * 2 + 1], pl, vh[2], vh[3]);
            }
        }
        const int r0 = wrp * 16 + (lane >> 2);
        const int cbase = (lane & 3) * 2;
#pragma unroll
        for (int hh = 0; hh < 2; hh++) {
            const int row = r0 + hh * 8;
            if (row < TWIN) {
                const int n = (wh * 7 + row / 7) * GW + ww * 7 + (row % 7);
                const size_t base = ((size_t)b * HW + n) * 256 + h * 32;
#pragma unroll
                for (int nt = 0; nt < 4; nt++) {
                    const int col = nt * 8 + cbase;
                    __nv_bfloat16 h0, l0, h1, l1;
                    cvt2(oacc[nt][hh * 2], h0, l0);
                    cvt2(oacc[nt][hh * 2 + 1], h1, l1);
                    *(__nv_bfloat162*)(g_Bh + base + col) = __halves2bfloat162(h0, h1);
                    *(__nv_bfloat162*)(g_Bl + base + col) = __halves2bfloat162(l0, l1);
                }
            }
        }
    }
}

// ---------------- upd attention: spatial queries x 16 added keys ------------
#define KV_HS 548
__global__ void __launch_bounds__(256) updattn_k()
{
    __shared__ float ksm[8 * KV_HS], vsm[8 * KV_HS];
    const int blk = blockIdx.x;
    const int b = blk / 392;
    const int tok0 = (blk % 392) * 32;
    const int tid = threadIdx.x;

    for (int e = tid; e < 16 * 256; e += 256) {
        const int j = e >> 8, c = e & 255;
        const int h = c >> 5, d = c & 31;
        const size_t src = ((size_t)b * NTOK + HW + j) * 768 + 256 + c;
        ksm[h * KV_HS + j * 34 + d] = g_qkv1[src];
        vsm[h * KV_HS + j * 34 + d] = g_qkv1[src + 256];
    }
    __syncthreads();

    const int tl = tid >> 3, h = tid & 7;
    const int n = tok0 + tl;
    const float* qp = g_qkv2 + ((size_t)b * HW + n) * 768 + h * 32;
    float qr[32];
#pragma unroll
    for (int d4 = 0; d4 < 8; d4++) {
        float4 v = *(const float4*)(qp + d4 * 4);
        qr[d4 * 4] = v.x; qr[d4 * 4 + 1] = v.y; qr[d4 * 4 + 2] = v.z; qr[d4 * 4 + 3] = v.w;
    }
    float s[16]; float m = -1e30f;
#pragma unroll
    for (int j = 0; j < 16; j++) {
        float a = 0.f;
        const float* kb = &ksm[h * KV_HS + j * 34];
#pragma unroll
        for (int d2 = 0; d2 < 16; d2++) {
            float2 kv = *(const float2*)(kb + d2 * 2);
            a += qr[d2 * 2] * kv.x + qr[d2 * 2 + 1] * kv.y;
        }
        s[j] = a * SCALE; m = fmaxf(m, s[j]);
    }
    float l = 0.f;
#pragma unroll
    for (int j = 0; j < 16; j++) { s[j] = __expf(s[j] - m); l += s[j]; }
    const float inv = 1.f / l;
    float outv[32];
#pragma unroll
    for (int d = 0; d < 32; d++) outv[d] = 0.f;
#pragma unroll
    for (int j = 0; j < 16; j++) {
        const float p = s[j] * inv;
        const float2* vb2 = (const float2*)&vsm[h * KV_HS + j * 34];
#pragma unroll
        for (int d2 = 0; d2 < 16; d2++) {
            const float2 v = vb2[d2];
            outv[d2 * 2]     += p * v.x;
            outv[d2 * 2 + 1] += p * v.y;
        }
    }
    const size_t off = ((size_t)b * HW + n) * 256 + h * 32;
#pragma unroll
    for (int d2 = 0; d2 < 16; d2++) {
        __nv_bfloat16 h0, l0, h1, l1;
        cvt2(outv[d2 * 2], h0, l0); cvt2(outv[d2 * 2 + 1], h1, l1);
        *(__nv_bfloat162*)(g_Bh + off + d2 * 2) = __halves2bfloat162(h0, h1);
        *(__nv_bfloat162*)(g_Bl + off + d2 * 2) = __halves2bfloat162(l0, l1);
    }
}

// ---------------- o_add flash attention: 16 queries over 12544 keys ---------
#define OA_KT 112
#define OA_SMEM ((528 + 3696 + 3696 + 1792 + 48) * 4)
__global__ void __launch_bounds__(256) oadd_attn_k()
{
    extern __shared__ float sm[];
    float* qsm  = sm;
    float* Kt   = sm + 528;
    float* Vt   = Kt + 3696;
    float* P    = Vt + 3696;
    float* mrow = P + 1792;
    float* lrow = mrow + 16;
    float* alpha = lrow + 16;

    const int blk = blockIdx.x;
    const int split = blk & 15;
    const int h = (blk >> 4) & 7;
    const int b = blk >> 7;
    const int tid = threadIdx.x;
    const int lane = tid & 31, wrp = tid >> 5;

    if (tid < 16 * 32) {
        const int qi = tid >> 5, d = tid & 31;
        qsm[qi * 33 + d] = g_qkv1[((size_t)b * NTOK + HW + qi) * 768 + h * 32 + d];
    }
    if (tid < 16) { mrow[tid] = -1e30f; lrow[tid] = 0.f; }
    __syncthreads();

    float acc0 = 0.f, acc1 = 0.f;

    const int key0 = split * 784;
    for (int t0 = 0; t0 < 784; t0 += OA_KT) {
        for (int e = tid; e < OA_KT * 32; e += 256) {
            const int j = e >> 5, d = e & 31;
            const size_t src = ((size_t)b * HW + key0 + t0 + j) * 768 + h * 32 + d;
            Kt[j * 33 + d] = g_qkv2[src + 256];
            Vt[j * 33 + d] = g_qkv2[src + 512];
        }
        __syncthreads();
        {
            const int qi = tid & 15, jb = tid >> 4;
            float qr[32];
#pragma unroll
            for (int d = 0; d < 32; d++) qr[d] = qsm[qi * 33 + d];
#pragma unroll
            for (int jj = 0; jj < 7; jj++) {
                const int j = jb * 7 + jj;
                float s = 0.f;
#pragma unroll
                for (int d = 0; d < 32; d++) s += qr[d] * Kt[j * 33 + d];
                P[qi * OA_KT + j] = s * SCALE;
            }
        }
        __syncthreads();
#pragma unroll
        for (int rr = 0; rr < 2; rr++) {
            const int qi = wrp * 2 + rr;
            float m = -1e30f;
            for (int j = lane; j < OA_KT; j += 32) m = fmaxf(m, P[qi * OA_KT + j]);
#pragma unroll
            for (int o = 16; o > 0; o >>= 1) m = fmaxf(m, __shfl_xor_sync(~0u, m, o));
            const float mold = mrow[qi];
            const float mnew = fmaxf(m, mold);
            float s = 0.f;
            for (int j = lane; j < OA_KT; j += 32) {
                const float e = __expf(P[qi * OA_KT + j] - mnew);
                P[qi * OA_KT + j] = e; s += e;
            }
#pragma unroll
            for (int o = 16; o > 0; o >>= 1) s += __shfl_xor_sync(~0u, s, o);
            if (lane == 0) {
                const float a = __expf(mold - mnew);
                alpha[qi] = a;
                lrow[qi] = lrow[qi] * a + s;
                mrow[qi] = mnew;
            }
        }
        __syncthreads();
        {
            const float a0 = alpha[wrp], a1 = alpha[wrp + 8];
            acc0 *= a0; acc1 *= a1;
            const float* P0 = P + wrp * OA_KT;
            const float* P1 = P + (wrp + 8) * OA_KT;
            for (int j = 0; j < OA_KT; j++) {
                const float vv = Vt[j * 33 + lane];
                acc0 += P0[j] * vv;
                acc1 += P1[j] * vv;
            }
        }
        __syncthreads();
    }
    const size_t pbase = (size_t)blk * 16 * 34;
    g_part[pbase + wrp * 34 + 2 + lane]       = acc0;
    g_part[pbase + (wrp + 8) * 34 + 2 + lane] = acc1;
    if (tid < 16) {
        g_part[pbase + tid * 34 + 0] = mrow[tid];
        g_part[pbase + tid * 34 + 1] = lrow[tid];
    }
}

__global__ void oadd_combine_k()
{
    const int bh = blockIdx.x;
    const int h = bh & 7, b = bh >> 3;
    const int tid = threadIdx.x;
    const int qi = tid >> 5, d = tid & 31;
    float M = -1e30f;
    for (int s = 0; s < 16; s++)
        M = fmaxf(M, g_part[(((size_t)bh * 16 + s) * 16 + qi) * 34]);
    float L = 0.f, val = 0.f;
    for (int s = 0; s < 16; s++) {
        const size_t base = (((size_t)bh * 16 + s) * 16 + qi) * 34;
        const float w = __expf(g_part[base] - M);
        L += g_part[base + 1] * w;
        val += g_part[base + 2 + d] * w;
    }
    g_oadd[((size_t)b * 16 + qi) * 256 + h * 32 + d] = val / L;
}

// ---------------- tiny proj for the 128 added-token rows --------------------
__global__ void __launch_bounds__(256) oadd_proj_k(const float* __restrict__ pw,
                                                   const float* __restrict__ pb,
                                                   float* __restrict__ out)
{
    __shared__ float xin[256];
    const int row = blockIdx.x;
    const int b = row >> 4, qi = row & 15;
    const int tid = threadIdx.x;
    xin[tid] = g_oadd[(size_t)row * 256 + tid];
    __syncthreads();
    const float* wr = pw + (size_t)tid * 256;
    float s = 0.f;
    for (int k = 0; k < 256; k += 4) {
        float4 w4 = *(const float4*)(wr + k);
        s += xin[k] * w4.x + xin[k + 1] * w4.y + xin[k + 2] * w4.z + xin[k + 3] * w4.w;
    }
    out[((size_t)b * NTOK + HW + qi) * 256 + tid] = s + pb[tid];
}

// ---------------- launch ----------------------------------------------------
extern "C" void kernel_launch(void* const* d_in, const int* in_sizes, int n_in,
                              void* d_out, int out_size)
{
    const float* x       = (const float*)d_in[0];
    const int*   pos2d   = (const int*)d_in[1];
    const float* qkv_w   = (const float*)d_in[3];
    const float* qkv_b   = (const float*)d_in[4];
    const float* proj_w  = (const float*)d_in[5];
    const float* proj_b  = (const float*)d_in[6];
    float* out = (float*)d_out;

    float *qkv1, *qkv2;
    __nv_bfloat16 *ah, *al, *bh, *bl, *wqh, *wql, *wph, *wpl;
    cudaGetSymbolAddress((void**)&qkv1,  g_qkv1);
    cudaGetSymbolAddress((void**)&qkv2,  g_qkv2);
    cudaGetSymbolAddress((void**)&ah,  g_Ah);
    cudaGetSymbolAddress((void**)&al,  g_Al);
    cudaGetSymbolAddress((void**)&bh,  g_Bh);
    cudaGetSymbolAddress((void**)&bl,  g_Bl);
    cudaGetSymbolAddress((void**)&wqh, g_Wqh);
    cudaGetSymbolAddress((void**)&wql, g_Wql);
    cudaGetSymbolAddress((void**)&wph, g_Wph);
    cudaGetSymbolAddress((void**)&wpl, g_Wpl);

    cudaFuncSetAttribute(tgemm_k, cudaFuncAttributeMaxDynamicSharedMemorySize, GSM_TOT);
    cudaFuncSetAttribute(winattn_k, cudaFuncAttributeMaxDynamicSharedMemorySize, WA_SMEM);
    cudaFuncSetAttribute(oadd_attn_k, cudaFuncAttributeMaxDynamicSharedMemorySize, OA_SMEM);

    // launch order keeps winattn_k 4th (ncu capture slot)
    conv_pair_k<<<192, 256>>>(qkv_w,  wqh, wql, 768 * 64);
    conv_pair_k<<<25120, 256>>>(x, ah, al, 100480 * 64);
    tgemm_k<<<dim3(6, 785), 256, GSM_TOT>>>(ah, al, wqh, wql, qkv_b, qkv1,
                                            nullptr, nullptr, 768, 0);
    winattn_k<<<2048 * 8, 128, WA_SMEM>>>(pos2d);
    conv_pair_k<<<64,  256>>>(proj_w, wph, wpl, 256 * 64);
    tgemm_k<<<dim3(2, 784), 256, GSM_TOT>>>(bh, bl, wph, wpl, proj_b, out,
                                            ah, al, 256, 1);
    tgemm_k<<<dim3(6, 784), 256, GSM_TOT>>>(ah, al, wqh, wql, qkv_b, qkv2,
                                            nullptr, nullptr, 768, 0);
    oadd_attn_k<<<1024, 256, OA_SMEM>>>();
    oadd_combine_k<<<64, 512>>>();
    updattn_k<<<3136, 256>>>();
    tgemm_k<<<dim3(2, 784), 256, GSM_TOT>>>(bh, bl, wph, wpl, proj_b, out,
                                            nullptr, nullptr, 256, 2);
    oadd_proj_k<<<128, 256>>>(proj_w, proj_b, out);
}

// round 13
// speedup vs baseline: 1.1339x; 1.1339x over previous
#include <cuda_runtime.h>
#include <cuda_bf16.h>
#include <cstdint>

#define BB 8
#define NTOK 12560
#define HW 12544
#define CDIM 256
#define NADD 16
#define NHEAD 8
#define HD 32
#define GW 112
#define TWIN 49
#define SCALE 0.17677669529663687f

// ---------------- scratch (device globals; no allocations allowed) ----------
__device__ float g_qkv1[(size_t)BB * NTOK * 768];
__device__ float g_qkv2[(size_t)BB * HW * 768];
__device__ float g_part[1024 * 16 * 34];
__device__ float g_oadd[BB * NADD * CDIM];
// bf16 split operands
__device__ __nv_bfloat16 g_Ah[(size_t)100480 * 256];
__device__ __nv_bfloat16 g_Al[(size_t)100480 * 256];
__device__ __nv_bfloat16 g_Bh[(size_t)100352 * 256];
__device__ __nv_bfloat16 g_Bl[(size_t)100352 * 256];
__device__ __nv_bfloat16 g_Wqh[768 * 256], g_Wql[768 * 256];
__device__ __nv_bfloat16 g_Wph[256 * 256], g_Wpl[256 * 256];

__constant__ float c_rope_inv[8] = {
    1.0f, 0.5623413251903491f, 0.31622776601683794f, 0.17782794100389228f,
    0.1f, 0.05623413251903491f, 0.031622776601683794f, 0.017782794100389227f};

// ================= fp32 -> (bf16 hi, bf16 lo) split =========================
__device__ __forceinline__ void cvt2(float v, __nv_bfloat16& h, __nv_bfloat16& l) {
    h = __float2bfloat16_rn(v);
    l = __float2bfloat16_rn(v - __bfloat162float(h));
}
__global__ void conv_pair_k(const float* __restrict__ src,
                            __nv_bfloat16* __restrict__ dh,
                            __nv_bfloat16* __restrict__ dl,
                            int n4)
{
    const int i = blockIdx.x * 256 + threadIdx.x;
    if (i >= n4) return;
    const int e0 = i * 4;
    const float4 v = *(const float4*)(src + e0);
    __nv_bfloat16 h0, l0, h1, l1, h2, l2, h3, l3;
    cvt2(v.x, h0, l0); cvt2(v.y, h1, l1); cvt2(v.z, h2, l2); cvt2(v.w, h3, l3);
    __nv_bfloat162* ph = (__nv_bfloat162*)(dh + e0);
    __nv_bfloat162* pl = (__nv_bfloat162*)(dl + e0);
    ph[0] = __halves2bfloat162(h0, h1); ph[1] = __halves2bfloat162(h2, h3);
    pl[0] = __halves2bfloat162(l0, l1); pl[1] = __halves2bfloat162(l2, l3);
}

// ================= shared PTX helpers ========================================
#define CP16(saddr, gptr) \
    asm volatile("cp.async.ca.shared.global [%0], [%1], 16;" :: "r"(saddr), "l"(gptr))
#define CP_COMMIT() asm volatile("cp.async.commit_group;")
#define CP_WAIT1()  asm volatile("cp.async.wait_group 1;")
#define CP_WAIT0()  asm volatile("cp.async.wait_group 0;")

#define LDMX4(r0_, r1_, r2_, r3_, addr_) \
    asm volatile("ldmatrix.sync.aligned.m8n8.x4.shared.b16 {%0,%1,%2,%3}, [%4];" \
        : "=r"(r0_), "=r"(r1_), "=r"(r2_), "=r"(r3_) : "r"(addr_))

#define MMA16816(c_, a_, b0_, b1_) \
    asm volatile("mma.sync.aligned.m16n8k16.row.col.f32.bf16.bf16.f32 " \
        "{%0,%1,%2,%3}, {%4,%5,%6,%7}, {%8,%9}, {%0,%1,%2,%3};" \
        : "+f"((c_)[0]), "+f"((c_)[1]), "+f"((c_)[2]), "+f"((c_)[3]) \
        : "r"((a_)[0]), "r"((a_)[1]), "r"((a_)[2]), "r"((a_)[3]), \
          "r"(b0_), "r"(b1_))

__device__ __forceinline__ uint32_t smem_u32(const void* p) {
    uint32_t a;
    asm("{ .reg .u64 t; cvta.to.shared.u64 t, %1; cvt.u32.u64 %0, t; }" : "=r"(a) : "l"(p));
    return a;
}

// ================= mma.sync bf16x3 GEMM =====================================
#define MATB 10240
#define BUFB (4 * MATB)
#define GSM_TOT (1024 + 2 * BUFB)

__global__ void __launch_bounds__(256, 2) tgemm_k(
    const __nv_bfloat16* __restrict__ Ah, const __nv_bfloat16* __restrict__ Al,
    const __nv_bfloat16* __restrict__ Wh, const __nv_bfloat16* __restrict__ Wl,
    const float* __restrict__ bias, float* __restrict__ Out,
    __nv_bfloat16* __restrict__ oah, __nv_bfloat16* __restrict__ oal,
    int nout, int out_mode)
{
    extern __shared__ char smem[];
    float* sbias = (float*)smem;
    const int tid = threadIdx.x;
    const int lane = tid & 31, wid = tid >> 5;
    const int wm = wid & 3, wn = wid >> 2;
    const int c0 = blockIdx.x * 128, r0 = blockIdx.y * 128;

    if (tid < 128) sbias[tid] = bias[c0 + tid];

    const uint32_t sbase = smem_u32(smem) + 1024;
    const int ldrow = tid >> 2;
    const int ldseg = tid & 3;

    auto load_chunk = [&](int ck, int buf) {
        const uint32_t b = sbase + buf * BUFB;
        const int koff = ck * 32 + ldseg * 8;
#pragma unroll
        for (int i = 0; i < 2; i++) {
            const int row = ldrow + i * 64;
            const uint32_t so = row * 80 + ldseg * 16;
            const size_t ga = (size_t)(r0 + row) * 256 + koff;
            const size_t gw = (size_t)(c0 + row) * 256 + koff;
            CP16(b + 0 * MATB + so, Ah + ga);
            CP16(b + 1 * MATB + so, Al + ga);
            CP16(b + 2 * MATB + so, Wh + gw);
            CP16(b + 3 * MATB + so, Wl + gw);
        }
        CP_COMMIT();
    };

    float acc[2][8][4];
#pragma unroll
    for (int i = 0; i < 2; i++)
#pragma unroll
        for (int j = 0; j < 8; j++)
#pragma unroll
            for (int k = 0; k < 4; k++) acc[i][j][k] = 0.f;

    load_chunk(0, 0);

    for (int ck = 0; ck < 8; ck++) {
        if (ck < 7) load_chunk(ck + 1, (ck + 1) & 1);
        if (ck < 7) { CP_WAIT1(); } else { CP_WAIT0(); }
        __syncthreads();

        const uint32_t b = sbase + (ck & 1) * BUFB;
        const int arow = wm * 32 + (lane & 15);
        const int acol8 = (lane >> 4) * 8;
        const int nrow = wn * 64 + ((lane >> 4) << 3) + (lane & 7);
        const int kcol8 = ((lane >> 3) & 1) * 8;

#pragma unroll
        for (int ks = 0; ks < 2; ks++) {
            const int kc = ks * 16;
            uint32_t ah[2][4], al[2][4];
#pragma unroll
            for (int mf = 0; mf < 2; mf++) {
                const uint32_t aaddr = b + (uint32_t)(arow + mf * 16) * 80 + (uint32_t)(kc + acol8) * 2;
                LDMX4(ah[mf][0], ah[mf][1], ah[mf][2], ah[mf][3], aaddr);
                LDMX4(al[mf][0], al[mf][1], al[mf][2], al[mf][3], aaddr + MATB);
            }
#pragma unroll
            for (int nf2 = 0; nf2 < 4; nf2++) {
                const uint32_t waddr = b + 2 * MATB
                    + (uint32_t)(nrow + nf2 * 16) * 80 + (uint32_t)(kc + kcol8) * 2;
                uint32_t wh[4], wl[4];
                LDMX4(wh[0], wh[1], wh[2], wh[3], waddr);
                LDMX4(wl[0], wl[1], wl[2], wl[3], waddr + MATB);
#pragma unroll
                for (int mf = 0; mf < 2; mf++) {
                    MMA16816(acc[mf][nf2 * 2],     ah[mf], wh[0], wh[1]);
                    MMA16816(acc[mf][nf2 * 2 + 1], ah[mf], wh[2], wh[3]);
                    MMA16816(acc[mf][nf2 * 2],     ah[mf], wl[0], wl[1]);
                    MMA16816(acc[mf][nf2 * 2 + 1], ah[mf], wl[2], wl[3]);
                    MMA16816(acc[mf][nf2 * 2],     al[mf], wh[0], wh[1]);
                    MMA16816(acc[mf][nf2 * 2 + 1], al[mf], wh[2], wh[3]);
                }
            }
        }
        __syncthreads();
    }

    // ---- epilogue ----
#pragma unroll
    for (int mf = 0; mf < 2; mf++) {
        const int rA = r0 + wm * 32 + mf * 16 + (lane >> 2);
#pragma unroll
        for (int nf = 0; nf < 8; nf++) {
            const int cb = wn * 64 + nf * 8 + (lane & 3) * 2;
            const float bv0 = sbias[cb], bv1 = sbias[cb + 1];
#pragma unroll
            for (int hh = 0; hh < 2; hh++) {
                const int r = rA + hh * 8;
                size_t ob;
                if (out_mode == 0) ob = (size_t)r * nout + c0 + cb;
                else               ob = ((size_t)r + (size_t)(r / HW) * NADD) * 256 + c0 + cb;
                const float v0 = acc[mf][nf][hh * 2]     + bv0;
                const float v1 = acc[mf][nf][hh * 2 + 1] + bv1;
                if (out_mode == 2) {
                    float2 o = *(float2*)(Out + ob);
                    o.x += 0.5f * v0; o.y += 0.5f * v1;
                    *(float2*)(Out + ob) = o;
                } else {
                    *(float2*)(Out + ob) = make_float2(v0, v1);
                    if (out_mode == 1) {
                        __nv_bfloat16 h0, l0, h1, l1;
                        cvt2(v0, h0, l0); cvt2(v1, h1, l1);
                        const size_t db = (size_t)r * 256 + c0 + cb;
                        *(__nv_bfloat162*)(oah + db) = __halves2bfloat162(h0, h1);
                        *(__nv_bfloat162*)(oal + db) = __halves2bfloat162(l0, l1);
                    }
                }
            }
        }
    }
}

// ---------------- windowed attention (rope fused): block = (window, head) ---
// (round-9 scalar variant: measured 414us, 62 regs, issue 71.4%)
#define WPAD 36
__global__ void __launch_bounds__(256) winattn_k(const int* __restrict__ pos2d)
{
    __shared__ float qs[TWIN * WPAD], ks[TWIN * WPAD], vs[TWIN * WPAD];
    __shared__ float S[TWIN * 49];
    const int h = blockIdx.x & 7;
    const int wid = blockIdx.x >> 3;
    const int b = wid >> 8;
    const int w = wid & 255;
    const int wh = w >> 4, ww = w & 15;
    const int tid = threadIdx.x, lane = tid & 31, wrp = tid >> 5;

    for (int e = tid; e < TWIN * 24; e += 256) {
        const int t = e / 24, seg = e % 24;
        const int mat = seg >> 3, d4 = seg & 7;
        const int n = (wh * 7 + t / 7) * GW + ww * 7 + (t % 7);
        const float4 v = *(const float4*)(g_qkv1 + ((size_t)b * NTOK + n) * 768
                                          + h * 32 + mat * 256 + d4 * 4);
        float* dst = (mat == 0) ? qs : ((mat == 1) ? ks : vs);
        *(float4*)&dst[t * WPAD + d4 * 4] = v;
    }
    __syncthreads();

    for (int e = tid; e < TWIN * 16; e += 256) {
        const int t = e >> 4, pi = e & 15;
        const int hh = pi >> 3, i = pi & 7;
        const int n = (wh * 7 + t / 7) * GW + ww * 7 + (t % 7);
        const int pos = pos2d[((size_t)b * NTOK + n) * 2 + hh];
        float sn, cs;
        sincosf((float)pos * c_rope_inv[i], &sn, &cs);
        const int base = t * WPAD + hh * 16 + i;
        const float q0 = qs[base], q1 = qs[base + 8];
        qs[base] = q0 * cs - q1 * sn; qs[base + 8] = q1 * cs + q0 * sn;
        const float k0 = ks[base], k1 = ks[base + 8];
        ks[base] = k0 * cs - k1 * sn; ks[base + 8] = k1 * cs + k0 * sn;
    }
    __syncthreads();

    {
        const int qi = tid & 63, quarter = tid >> 6;
        if (qi < TWIN) {
            float qr[32];
#pragma unroll
            for (int d4 = 0; d4 < 8; d4++) {
                float4 v = *(float4*)&qs[qi * WPAD + d4 * 4];
                qr[d4 * 4] = v.x; qr[d4 * 4 + 1] = v.y;
                qr[d4 * 4 + 2] = v.z; qr[d4 * 4 + 3] = v.w;
            }
            const int j0 = (quarter * 49) >> 2, j1 = ((quarter + 1) * 49) >> 2;
            for (int j = j0; j < j1; j++) {
                float s = 0.f;
#pragma unroll
                for (int d4 = 0; d4 < 8; d4++) {
                    float4 kk = *(float4*)&ks[j * WPAD + d4 * 4];
                    s += qr[d4 * 4] * kk.x + qr[d4 * 4 + 1] * kk.y
                       + qr[d4 * 4 + 2] * kk.z + qr[d4 * 4 + 3] * kk.w;
                }
                S[qi * 49 + j] = s * SCALE;
            }
        }
    }
    __syncthreads();

#pragma unroll
    for (int rr = 0; rr < 7; rr++) {
        const int row = wrp + 8 * rr;
        if (row < TWIN) {
            const float v0 = S[row * 49 + lane];
            const float v1 = (lane + 32 < 49) ? S[row * 49 + lane + 32] : -1e30f;
            float m = fmaxf(v0, v1);
#pragma unroll
            for (int o = 16; o > 0; o >>= 1) m = fmaxf(m, __shfl_xor_sync(~0u, m, o));
            const float e0 = __expf(v0 - m);
            const float e1 = (lane + 32 < 49) ? __expf(v1 - m) : 0.f;
            float s = e0 + e1;
#pragma unroll
            for (int o = 16; o > 0; o >>= 1) s += __shfl_xor_sync(~0u, s, o);
            const float inv = 1.f / s;
            S[row * 49 + lane] = e0 * inv;
            if (lane + 32 < 49) S[row * 49 + lane + 32] = e1 * inv;
        }
    }
    __syncthreads();

    float acc[7];
#pragma unroll
    for (int t = 0; t < 7; t++) acc[t] = 0.f;
    for (int j = 0; j < TWIN; j++) {
        const float vv = vs[j * WPAD + lane];
#pragma unroll
        for (int t = 0; t < 7; t++) {
            const int i = wrp + 8 * t;
            if (i < TWIN) acc[t] += S[i * 49 + j] * vv;
        }
    }
#pragma unroll
    for (int t = 0; t < 7; t++) {
        const int i = wrp + 8 * t;
        if (i < TWIN) {
            const float v0 = acc[t];
            const float v1 = __shfl_down_sync(~0u, v0, 1);
            if (!(lane & 1)) {
                const int n = (wh * 7 + i / 7) * GW + ww * 7 + (i % 7);
                __nv_bfloat16 h0, l0, h1, l1;
                cvt2(v0, h0, l0); cvt2(v1, h1, l1);
                const size_t o = ((size_t)b * HW + n) * 256 + h * 32 + lane;
                *(__nv_bfloat162*)(g_Bh + o) = __halves2bfloat162(h0, h1);
                *(__nv_bfloat162*)(g_Bl + o) = __halves2bfloat162(l0, l1);
            }
        }
    }
}

// ---------------- upd attention: spatial queries x 16 added keys ------------
#define KV_HS 548
__global__ void __launch_bounds__(256) updattn_k()
{
    __shared__ float ksm[8 * KV_HS], vsm[8 * KV_HS];
    const int blk = blockIdx.x;
    const int b = blk / 392;
    const int tok0 = (blk % 392) * 32;
    const int tid = threadIdx.x;

    for (int e = tid; e < 16 * 256; e += 256) {
        const int j = e >> 8, c = e & 255;
        const int h = c >> 5, d = c & 31;
        const size_t src = ((size_t)b * NTOK + HW + j) * 768 + 256 + c;
        ksm[h * KV_HS + j * 34 + d] = g_qkv1[src];
        vsm[h * KV_HS + j * 34 + d] = g_qkv1[src + 256];
    }
    __syncthreads();

    const int tl = tid >> 3, h = tid & 7;
    const int n = tok0 + tl;
    const float* qp = g_qkv2 + ((size_t)b * HW + n) * 768 + h * 32;
    float qr[32];
#pragma unroll
    for (int d4 = 0; d4 < 8; d4++) {
        float4 v = *(const float4*)(qp + d4 * 4);
        qr[d4 * 4] = v.x; qr[d4 * 4 + 1] = v.y; qr[d4 * 4 + 2] = v.z; qr[d4 * 4 + 3] = v.w;
    }
    float s[16]; float m = -1e30f;
#pragma unroll
    for (int j = 0; j < 16; j++) {
        float a = 0.f;
        const float* kb = &ksm[h * KV_HS + j * 34];
#pragma unroll
        for (int d2 = 0; d2 < 16; d2++) {
            float2 kv = *(const float2*)(kb + d2 * 2);
            a += qr[d2 * 2] * kv.x + qr[d2 * 2 + 1] * kv.y;
        }
        s[j] = a * SCALE; m = fmaxf(m, s[j]);
    }
    float l = 0.f;
#pragma unroll
    for (int j = 0; j < 16; j++) { s[j] = __expf(s[j] - m); l += s[j]; }
    const float inv = 1.f / l;
    float outv[32];
#pragma unroll
    for (int d = 0; d < 32; d++) outv[d] = 0.f;
#pragma unroll
    for (int j = 0; j < 16; j++) {
        const float p = s[j] * inv;
        const float2* vb2 = (const float2*)&vsm[h * KV_HS + j * 34];
#pragma unroll
        for (int d2 = 0; d2 < 16; d2++) {
            const float2 v = vb2[d2];
            outv[d2 * 2]     += p * v.x;
            outv[d2 * 2 + 1] += p * v.y;
        }
    }
    const size_t off = ((size_t)b * HW + n) * 256 + h * 32;
#pragma unroll
    for (int d2 = 0; d2 < 16; d2++) {
        __nv_bfloat16 h0, l0, h1, l1;
        cvt2(outv[d2 * 2], h0, l0); cvt2(outv[d2 * 2 + 1], h1, l1);
        *(__nv_bfloat162*)(g_Bh + off + d2 * 2) = __halves2bfloat162(h0, h1);
        *(__nv_bfloat162*)(g_Bl + off + d2 * 2) = __halves2bfloat162(l0, l1);
    }
}

// ---------------- o_add flash attention: 16 queries over 12544 keys ---------
#define OA_KT 112
#define OA_SMEM ((528 + 3696 + 3696 + 1792 + 48) * 4)
__global__ void __launch_bounds__(256) oadd_attn_k()
{
    extern __shared__ float sm[];
    float* qsm  = sm;
    float* Kt   = sm + 528;
    float* Vt   = Kt + 3696;
    float* P    = Vt + 3696;
    float* mrow = P + 1792;
    float* lrow = mrow + 16;
    float* alpha = lrow + 16;

    const int blk = blockIdx.x;
    const int split = blk & 15;
    const int h = (blk >> 4) & 7;
    const int b = blk >> 7;
    const int tid = threadIdx.x;
    const int lane = tid & 31, wrp = tid >> 5;

    if (tid < 16 * 32) {
        const int qi = tid >> 5, d = tid & 31;
        qsm[qi * 33 + d] = g_qkv1[((size_t)b * NTOK + HW + qi) * 768 + h * 32 + d];
    }
    if (tid < 16) { mrow[tid] = -1e30f; lrow[tid] = 0.f; }
    __syncthreads();

    float acc0 = 0.f, acc1 = 0.f;

    const int key0 = split * 784;
    for (int t0 = 0; t0 < 784; t0 += OA_KT) {
        for (int e = tid; e < OA_KT * 32; e += 256) {
            const int j = e >> 5, d = e & 31;
            const size_t src = ((size_t)b * HW + key0 + t0 + j) * 768 + h * 32 + d;
            Kt[j * 33 + d] = g_qkv2[src + 256];
            Vt[j * 33 + d] = g_qkv2[src + 512];
        }
        __syncthreads();
        {
            const int qi = tid & 15, jb = tid >> 4;
            float qr[32];
#pragma unroll
            for (int d = 0; d < 32; d++) qr[d] = qsm[qi * 33 + d];
#pragma unroll
            for (int jj = 0; jj < 7; jj++) {
                const int j = jb * 7 + jj;
                float s = 0.f;
#pragma unroll
                for (int d = 0; d < 32; d++) s += qr[d] * Kt[j * 33 + d];
                P[qi * OA_KT + j] = s * SCALE;
            }
        }
        __syncthreads();
#pragma unroll
        for (int rr = 0; rr < 2; rr++) {
            const int qi = wrp * 2 + rr;
            float m = -1e30f;
            for (int j = lane; j < OA_KT; j += 32) m = fmaxf(m, P[qi * OA_KT + j]);
#pragma unroll
            for (int o = 16; o > 0; o >>= 1) m = fmaxf(m, __shfl_xor_sync(~0u, m, o));
            const float mold = mrow[qi];
            const float mnew = fmaxf(m, mold);
            float s = 0.f;
            for (int j = lane; j < OA_KT; j += 32) {
                const float e = __expf(P[qi * OA_KT + j] - mnew);
                P[qi * OA_KT + j] = e; s += e;
            }
#pragma unroll
            for (int o = 16; o > 0; o >>= 1) s += __shfl_xor_sync(~0u, s, o);
            if (lane == 0) {
                const float a = __expf(mold - mnew);
                alpha[qi] = a;
                lrow[qi] = lrow[qi] * a + s;
                mrow[qi] = mnew;
            }
        }
        __syncthreads();
        {
            const float a0 = alpha[wrp], a1 = alpha[wrp + 8];
            acc0 *= a0; acc1 *= a1;
            const float* P0 = P + wrp * OA_KT;
            const float* P1 = P + (wrp + 8) * OA_KT;
            for (int j = 0; j < OA_KT; j++) {
                const float vv = Vt[j * 33 + lane];
                acc0 += P0[j] * vv;
                acc1 += P1[j] * vv;
            }
        }
        __syncthreads();
    }
    const size_t pbase = (size_t)blk * 16 * 34;
    g_part[pbase + wrp * 34 + 2 + lane]       = acc0;
    g_part[pbase + (wrp + 8) * 34 + 2 + lane] = acc1;
    if (tid < 16) {
        g_part[pbase + tid * 34 + 0] = mrow[tid];
        g_part[pbase + tid * 34 + 1] = lrow[tid];
    }
}

__global__ void oadd_combine_k()
{
    const int bh = blockIdx.x;
    const int h = bh & 7, b = bh >> 3;
    const int tid = threadIdx.x;
    const int qi = tid >> 5, d = tid & 31;
    float M = -1e30f;
    for (int s = 0; s < 16; s++)
        M = fmaxf(M, g_part[(((size_t)bh * 16 + s) * 16 + qi) * 34]);
    float L = 0.f, val = 0.f;
    for (int s = 0; s < 16; s++) {
        const size_t base = (((size_t)bh * 16 + s) * 16 + qi) * 34;
        const float w = __expf(g_part[base] - M);
        L += g_part[base + 1] * w;
        val += g_part[base + 2 + d] * w;
    }
    g_oadd[((size_t)b * 16 + qi) * 256 + h * 32 + d] = val / L;
}

// ---------------- tiny proj for the 128 added-token rows --------------------
__global__ void __launch_bounds__(256) oadd_proj_k(const float* __restrict__ pw,
                                                   const float* __restrict__ pb,
                                                   float* __restrict__ out)
{
    __shared__ float xin[256];
    const int row = blockIdx.x;
    const int b = row >> 4, qi = row & 15;
    const int tid = threadIdx.x;
    xin[tid] = g_oadd[(size_t)row * 256 + tid];
    __syncthreads();
    const float* wr = pw + (size_t)tid * 256;
    float s = 0.f;
    for (int k = 0; k < 256; k += 4) {
        float4 w4 = *(const float4*)(wr + k);
        s += xin[k] * w4.x + xin[k + 1] * w4.y + xin[k + 2] * w4.z + xin[k + 3] * w4.w;
    }
    out[((size_t)b * NTOK + HW + qi) * 256 + tid] = s + pb[tid];
}

// ---------------- launch ----------------------------------------------------
extern "C" void kernel_launch(void* const* d_in, const int* in_sizes, int n_in,
                              void* d_out, int out_size)
{
    const float* x       = (const float*)d_in[0];
    const int*   pos2d   = (const int*)d_in[1];
    const float* qkv_w   = (const float*)d_in[3];
    const float* qkv_b   = (const float*)d_in[4];
    const float* proj_w  = (const float*)d_in[5];
    const float* proj_b  = (const float*)d_in[6];
    float* out = (float*)d_out;

    float *qkv1, *qkv2;
    __nv_bfloat16 *ah, *al, *bh, *bl, *wqh, *wql, *wph, *wpl;
    cudaGetSymbolAddress((void**)&qkv1,  g_qkv1);
    cudaGetSymbolAddress((void**)&qkv2,  g_qkv2);
    cudaGetSymbolAddress((void**)&ah,  g_Ah);
    cudaGetSymbolAddress((void**)&al,  g_Al);
    cudaGetSymbolAddress((void**)&bh,  g_Bh);
    cudaGetSymbolAddress((void**)&bl,  g_Bl);
    cudaGetSymbolAddress((void**)&wqh, g_Wqh);
    cudaGetSymbolAddress((void**)&wql, g_Wql);
    cudaGetSymbolAddress((void**)&wph, g_Wph);
    cudaGetSymbolAddress((void**)&wpl, g_Wpl);

    cudaFuncSetAttribute(tgemm_k, cudaFuncAttributeMaxDynamicSharedMemorySize, GSM_TOT);
    cudaFuncSetAttribute(oadd_attn_k, cudaFuncAttributeMaxDynamicSharedMemorySize, OA_SMEM);

    // side stream + events for the post-qkv2 fork (created once; capturable)
    static cudaStream_t s1 = nullptr;
    static cudaEvent_t evFork = nullptr, evJoin = nullptr;
    if (s1 == nullptr) {
        cudaStreamCreateWithFlags(&s1, cudaStreamNonBlocking);
        cudaEventCreateWithFlags(&evFork, cudaEventDisableTiming);
        cudaEventCreateWithFlags(&evJoin, cudaEventDisableTiming);
    }

    // launch order keeps winattn_k 4th (ncu capture slot)
    conv_pair_k<<<192, 256>>>(qkv_w,  wqh, wql, 768 * 64);
    conv_pair_k<<<25120, 256>>>(x, ah, al, 100480 * 64);
    tgemm_k<<<dim3(6, 785), 256, GSM_TOT>>>(ah, al, wqh, wql, qkv_b, qkv1,
                                            nullptr, nullptr, 768, 0);
    winattn_k<<<2048 * 8, 256>>>(pos2d);
    conv_pair_k<<<64,  256>>>(proj_w, wph, wpl, 256 * 64);
    tgemm_k<<<dim3(2, 784), 256, GSM_TOT>>>(bh, bl, wph, wpl, proj_b, out,
                                            ah, al, 256, 1);
    tgemm_k<<<dim3(6, 784), 256, GSM_TOT>>>(ah, al, wqh, wql, qkv_b, qkv2,
                                            nullptr, nullptr, 768, 0);

    // fork: o_add chain on s1, upd chain on main stream
    cudaEventRecord(evFork, 0);
    cudaStreamWaitEvent(s1, evFork, 0);

    oadd_attn_k<<<1024, 256, OA_SMEM, s1>>>();
    oadd_combine_k<<<64, 512, 0, s1>>>();
    oadd_proj_k<<<128, 256, 0, s1>>>(proj_w, proj_b, out);
    cudaEventRecord(evJoin, s1);

    updattn_k<<<3136, 256>>>();
    tgemm_k<<<dim3(2, 784), 256, GSM_TOT>>>(bh, bl, wph, wpl, proj_b, out,
                                            nullptr, nullptr, 256, 2);

    // join
    cudaStreamWaitEvent(0, evJoin, 0);
}